// round 7
// baseline (speedup 1.0000x reference)
#include <cuda_runtime.h>
#include <cstdint>
#include <float.h>
#include <math.h>

#define D_DIM   2048
#define SK      64
#define NEXPERT 4096
#define TOPK    8
#define NMAX    8192

typedef unsigned long long ULL;

// S = x @ [W1;W2]^T, staged for the light topk kernel
__device__ float g_S[NMAX * 2 * SK];

__device__ __forceinline__ ULL pk2(float lo, float hi) {
    ULL r;
    asm("mov.b64 %0, {%1, %2};" : "=l"(r) : "f"(lo), "f"(hi));
    return r;
}
__device__ __forceinline__ void fma2(ULL& d, ULL a, ULL b) {
    asm("fma.rn.f32x2 %0, %1, %2, %0;" : "+l"(d) : "l"(a), "l"(b));
}

// ===========================================================================
// Fused kernel: fp32 GEMM (sequential-k, reference-correlated numerics)
//   + direct scores streaming.  BM=32, BN=128, BK=32, 256 thr, 256 CTAs
//   (2 waves -> wave-1 score stores overlap wave-2 compute).
// Warp w owns rows w*4..w*4+3 (all 128 cols); lane owns cols lane*4..+3.
// ===========================================================================
#define BMF  32
#define BKF  32
#define NCHF (D_DIM / BKF)   // 64

// smem: As[2][32][32] floats (8KB) + Bs[2][32][128] floats (32KB) = 40KB.
// After the k-loop the same memory is reused as stage[32][128] (16KB).
__shared__ float smraw[10240];

__global__ __launch_bounds__(256) void pkr_fused(
    const float* __restrict__ x,
    const float* __restrict__ W1,
    const float* __restrict__ W2,
    float* __restrict__ scores_out)
{
    float* Af = smraw;            // [buf][kk][row]  buf stride 1024 floats
    float* Bf = smraw + 2048;     // [buf][kk][col]  buf stride 4096 floats

    const int tid  = threadIdx.x;
    const int w    = tid >> 5;
    const int lane = tid & 31;
    const int bm0  = blockIdx.x * BMF;

    // A loader: row (0..31), k-quad kc
    const int ar = tid >> 3;
    const int akc = (tid & 3 << 0, (tid & 7) * 4);
    const float4* pa = (const float4*)(x + (size_t)(bm0 + ar) * D_DIM) + (tid & 7);
    // B loader: 4 jobs, rows 0..127
    const float4* pb[4];
    int brow[4], bkc[4];
    #pragma unroll
    for (int j = 0; j < 4; j++) {
        const int job = tid + 256 * j;
        brow[j] = job >> 3;
        bkc[j]  = (job & 7) * 4;
        const float* wsrc = (brow[j] < SK) ? (W1 + (size_t)brow[j] * D_DIM)
                                           : (W2 + (size_t)(brow[j] - SK) * D_DIM);
        pb[j] = (const float4*)wsrc + (job & 7);
    }
    const int akc4 = (tid & 7) * 4;

    ULL acc[4][2];
    #pragma unroll
    for (int i = 0; i < 4; i++) { acc[i][0] = 0ULL; acc[i][1] = 0ULL; }

    // ---- fill stage 0 ----
    {
        float4 a = pa[0];
        Af[(akc4 + 0) * BMF + ar] = a.x;
        Af[(akc4 + 1) * BMF + ar] = a.y;
        Af[(akc4 + 2) * BMF + ar] = a.z;
        Af[(akc4 + 3) * BMF + ar] = a.w;
        #pragma unroll
        for (int j = 0; j < 4; j++) {
            float4 b = pb[j][0];
            Bf[(bkc[j] + 0) * 128 + brow[j]] = b.x;
            Bf[(bkc[j] + 1) * 128 + brow[j]] = b.y;
            Bf[(bkc[j] + 2) * 128 + brow[j]] = b.z;
            Bf[(bkc[j] + 3) * 128 + brow[j]] = b.w;
        }
    }
    __syncthreads();

    for (int c = 0; c < NCHF; c++) {
        const int p = c & 1;
        const float* Ap = Af + p * 1024;
        const float* Bp = Bf + p * 4096;

        // prefetch chunk c+1
        float4 a_pf, b_pf[4];
        const bool has_next = (c + 1) < NCHF;
        if (has_next) {
            a_pf = pa[(c + 1) * 8];
            #pragma unroll
            for (int j = 0; j < 4; j++) b_pf[j] = pb[j][(c + 1) * 8];
        }

        // compute chunk c  (sequential k within the chunk, chunks ascending)
        #pragma unroll
        for (int kk = 0; kk < BKF; kk++) {
            float4 a4 = *(const float4*)&Ap[kk * BMF + w * 4];     // broadcast
            ulonglong2 bb = *(const ulonglong2*)&Bp[kk * 128 + lane * 4];
            ULL a0 = pk2(a4.x, a4.x), a1 = pk2(a4.y, a4.y);
            ULL a2 = pk2(a4.z, a4.z), a3 = pk2(a4.w, a4.w);
            fma2(acc[0][0], a0, bb.x); fma2(acc[0][1], a0, bb.y);
            fma2(acc[1][0], a1, bb.x); fma2(acc[1][1], a1, bb.y);
            fma2(acc[2][0], a2, bb.x); fma2(acc[2][1], a2, bb.y);
            fma2(acc[3][0], a3, bb.x); fma2(acc[3][1], a3, bb.y);
        }

        if (has_next) {
            const int q = p ^ 1;
            float* Aq = Af + q * 1024;
            float* Bq = Bf + q * 4096;
            Aq[(akc4 + 0) * BMF + ar] = a_pf.x;
            Aq[(akc4 + 1) * BMF + ar] = a_pf.y;
            Aq[(akc4 + 2) * BMF + ar] = a_pf.z;
            Aq[(akc4 + 3) * BMF + ar] = a_pf.w;
            #pragma unroll
            for (int j = 0; j < 4; j++) {
                Bq[(bkc[j] + 0) * 128 + brow[j]] = b_pf[j].x;
                Bq[(bkc[j] + 1) * 128 + brow[j]] = b_pf[j].y;
                Bq[(bkc[j] + 2) * 128 + brow[j]] = b_pf[j].z;
                Bq[(bkc[j] + 3) * 128 + brow[j]] = b_pf[j].w;
            }
            __syncthreads();
        }
    }
    __syncthreads();   // protect smem before reusing as stage

    // ---- stage S rows to smem + persist to g_S ----
    float* stage = smraw;   // [32][128]
    #pragma unroll
    for (int i = 0; i < 4; i++) {
        const int rl = w * 4 + i;
        ulonglong2 v; v.x = acc[i][0]; v.y = acc[i][1];
        *(ulonglong2*)&stage[rl * 128 + lane * 4] = v;
        *(ulonglong2*)&g_S[(size_t)(bm0 + rl) * (2 * SK) + lane * 4] = v;
    }
    __syncwarp();

    // ---- stream scores for this warp's 4 rows (HBM-write bound) ----
    if (scores_out) {
        const int j = (lane & 15) * 4;
        const int ihalf = lane >> 4;
        #pragma unroll
        for (int r = 0; r < 4; r++) {
            const int rl = w * 4 + r;
            const float4 s2q = *(const float4*)&stage[rl * 128 + SK + j];
            float* __restrict__ srow =
                scores_out + (size_t)(bm0 + rl) * NEXPERT;
            #pragma unroll 8
            for (int t = 0; t < 32; t++) {
                const int i = t * 2 + ihalf;
                const float s1 = stage[rl * 128 + i];
                float4 v4;
                v4.x = s1 + s2q.x; v4.y = s1 + s2q.y;
                v4.z = s1 + s2q.z; v4.w = s1 + s2q.w;
                __stcs((float4*)&srow[i * SK + j], v4);
            }
        }
    }
}

// ===========================================================================
// Light topk kernel: one warp per row, no score streaming.
// Decomposed top-8 (top8(s1) x top8(s2) -> 64 candidates), stable tie-breaks.
// ===========================================================================
__global__ __launch_bounds__(256) void pkr_topk_lite(
    float* __restrict__ idx_out,
    float* __restrict__ probs_out)
{
    __shared__ float sb[8][2 * SK];
    const int w    = threadIdx.x >> 5;
    const int lane = threadIdx.x & 31;
    const size_t row = (size_t)blockIdx.x * 8 + w;

    *(float4*)&sb[w][lane * 4] =
        *(const float4*)&g_S[row * (2 * SK) + lane * 4];
    __syncwarp();

    __shared__ float c1v[8][8], c2v[8][8];
    __shared__ int   c1i[8][8], c2i[8][8];
    {
        float a0 = sb[w][lane],      a1 = sb[w][lane + 32];
        int   i0 = lane,             i1 = lane + 32;
        float b0 = sb[w][SK + lane], b1 = sb[w][SK + lane + 32];
        int   j0 = lane,             j1 = lane + 32;
        #pragma unroll
        for (int r = 0; r < TOPK; r++) {
            float v; int i;
            if (a0 > a1 || (a0 == a1 && i0 < i1)) { v = a0; i = i0; }
            else                                  { v = a1; i = i1; }
            #pragma unroll
            for (int off = 16; off; off >>= 1) {
                float ov = __shfl_xor_sync(0xffffffffu, v, off);
                int   oi = __shfl_xor_sync(0xffffffffu, i, off);
                if (ov > v || (ov == v && oi < i)) { v = ov; i = oi; }
            }
            if (lane == r) { c1v[w][r] = v; c1i[w][r] = i; }
            if (i == i0) { a0 = -FLT_MAX; i0 = 1 << 30; }
            if (i == i1) { a1 = -FLT_MAX; i1 = 1 << 30; }
            float u; int jj;
            if (b0 > b1 || (b0 == b1 && j0 < j1)) { u = b0; jj = j0; }
            else                                  { u = b1; jj = j1; }
            #pragma unroll
            for (int off = 16; off; off >>= 1) {
                float ou = __shfl_xor_sync(0xffffffffu, u, off);
                int   oj = __shfl_xor_sync(0xffffffffu, jj, off);
                if (ou > u || (ou == u && oj < jj)) { u = ou; jj = oj; }
            }
            if (lane == r) { c2v[w][r] = u; c2i[w][r] = jj; }
            if (jj == j0) { b0 = -FLT_MAX; j0 = 1 << 30; }
            if (jj == j1) { b1 = -FLT_MAX; j1 = 1 << 30; }
        }
    }
    __syncwarp();

    const int p0 = lane, p1 = lane + 32;
    float cv0 = c1v[w][p0 >> 3] + c2v[w][p0 & 7];
    int   ci0 = c1i[w][p0 >> 3] * SK + c2i[w][p0 & 7];
    float cv1 = c1v[w][p1 >> 3] + c2v[w][p1 & 7];
    int   ci1 = c1i[w][p1 >> 3] * SK + c2i[w][p1 & 7];

    float mv[TOPK];
    int   mi[TOPK];
    #pragma unroll
    for (int r = 0; r < TOPK; r++) {
        float v; int i;
        if (cv0 > cv1 || (cv0 == cv1 && ci0 < ci1)) { v = cv0; i = ci0; }
        else                                        { v = cv1; i = ci1; }
        #pragma unroll
        for (int off = 16; off; off >>= 1) {
            float ov = __shfl_xor_sync(0xffffffffu, v, off);
            int   oi = __shfl_xor_sync(0xffffffffu, i, off);
            if (ov > v || (ov == v && oi < i)) { v = ov; i = oi; }
        }
        mv[r] = v; mi[r] = i;
        if (i == ci0) { cv0 = -FLT_MAX; ci0 = 1 << 30; }
        if (i == ci1) { cv1 = -FLT_MAX; ci1 = 1 << 30; }
    }

    if (lane == 0) {
        float m = mv[0], sum = 0.f, e[TOPK];
        #pragma unroll
        for (int r = 0; r < TOPK; r++) { e[r] = expf(mv[r] - m); sum += e[r]; }
        float inv = 1.f / sum;
        #pragma unroll
        for (int r = 0; r < TOPK; r++) {
            if (idx_out)   idx_out[row * TOPK + r]   = (float)mi[r];
            if (probs_out) probs_out[row * TOPK + r] = e[r] * inv;
        }
    }
}

// ---------------------------------------------------------------------------
extern "C" void kernel_launch(void* const* d_in, const int* in_sizes, int n_in,
                              void* d_out, int out_size) {
    const float* x  = (const float*)d_in[0];
    const float* W1 = (const float*)d_in[1];
    const float* W2 = (const float*)d_in[2];
    (void)n_in;

    int N = in_sizes[0] / D_DIM;   // 8192
    float* out = (float*)d_out;

    float* idxp = 0;
    float* probp = 0;
    float* scorep = 0;
    long long full = (long long)N * (2 * TOPK + NEXPERT);
    if ((long long)out_size == full) {
        idxp   = out;
        probp  = out + (long long)N * TOPK;
        scorep = out + (long long)N * 2 * TOPK;
    } else if ((long long)out_size == (long long)N * NEXPERT) {
        scorep = out;
    } else if ((long long)out_size == (long long)N * 2 * TOPK) {
        idxp  = out;
        probp = out + (long long)N * TOPK;
    } else {
        idxp   = out;
        probp  = out + (long long)N * TOPK;
        scorep = out + (long long)N * 2 * TOPK;
    }

    pkr_fused<<<N / BMF, 256>>>(x, W1, W2, scorep);
    pkr_topk_lite<<<N / 8, 256>>>(idxp, probp);
}

// round 8
// speedup vs baseline: 1.4735x; 1.4735x over previous
#include <cuda_runtime.h>
#include <float.h>
#include <math.h>

// Problem constants (fixed shapes from reference setup_inputs)
#define D_DIM   2048
#define SK      64       // sqrt_K
#define NEXPERT 4096     // SK*SK
#define TOPK    8
#define NMAX    8192

typedef unsigned long long ULL;

// Scratch for fused projection S = x @ [W1;W2]^T  -> [N, 128]
__device__ float g_S[NMAX * 2 * SK];

// ---------------------------------------------------------------------------
// packed f32x2 helpers (exact fp32; rt equals scalar FFMA but halves issues)
// ---------------------------------------------------------------------------
__device__ __forceinline__ ULL pk2(float lo, float hi) {
    ULL r;
    asm("mov.b64 %0, {%1, %2};" : "=l"(r) : "f"(lo), "f"(hi));
    return r;
}
__device__ __forceinline__ void fma2(ULL& d, ULL a, ULL b) {
    asm("fma.rn.f32x2 %0, %1, %2, %0;" : "+l"(d) : "l"(a), "l"(b));
}

// ---------------------------------------------------------------------------
// Kernel A (R2 verbatim — measured 140us, at the fp32 FMA-pipe floor):
// SGEMM  S[N,128] = x[N,2048] @ concat(W1,W2)[128,2048]^T
// BM=64 x BN=128, BK=16, 256 threads, double-buffered smem.
// Thread tile: 8 rows x 4 cols.  Warp covers 8 rows x all 128 cols.
// ---------------------------------------------------------------------------
#define BM 64
#define BN 128
#define BK 16
#define NIT (D_DIM / BK)

__global__ __launch_bounds__(256) void pkr_gemm(
    const float* __restrict__ x,
    const float* __restrict__ W1,
    const float* __restrict__ W2)
{
    __shared__ float As[2][BK][BM];   // 2 x 4 KB
    __shared__ float Bs[2][BK][BN];   // 2 x 8 KB

    const int tid  = threadIdx.x;
    const int w    = tid >> 5;
    const int lane = tid & 31;
    const int bm0  = blockIdx.x * BM;

    // A loader: row ar (0..63) coalesced along k; k offset akc in {0,4,8,12}
    const int ar  = tid >> 2;
    const int akc = (tid & 3) * 4;
    const float* xp = x + (size_t)(bm0 + ar) * D_DIM + akc;

    // B loader: col bc (0..63), k offset bkc in {0,4,8,12}
    const int bc  = tid & 63;
    const int bkc = (tid >> 6) * 4;
    const float* w1p = W1 + (size_t)bc * D_DIM + bkc;
    const float* w2p = W2 + (size_t)bc * D_DIM + bkc;

    ULL acc[8][2];
    #pragma unroll
    for (int i = 0; i < 8; i++) { acc[i][0] = 0ULL; acc[i][1] = 0ULL; }

    // stage 0 fill
    {
        float4 a  = *(const float4*)xp;
        float4 b1 = *(const float4*)w1p;
        float4 b2 = *(const float4*)w2p;
        As[0][akc + 0][ar] = a.x;  As[0][akc + 1][ar] = a.y;
        As[0][akc + 2][ar] = a.z;  As[0][akc + 3][ar] = a.w;
        Bs[0][bkc + 0][bc] = b1.x; Bs[0][bkc + 1][bc] = b1.y;
        Bs[0][bkc + 2][bc] = b1.z; Bs[0][bkc + 3][bc] = b1.w;
        Bs[0][bkc + 0][bc + SK] = b2.x; Bs[0][bkc + 1][bc + SK] = b2.y;
        Bs[0][bkc + 2][bc + SK] = b2.z; Bs[0][bkc + 3][bc + SK] = b2.w;
    }
    __syncthreads();

    int p = 0;
    float4 a_pf, b1_pf, b2_pf;
    for (int it = 0; it < NIT; ++it) {
        const bool has_next = (it + 1) < NIT;
        if (has_next) {
            const int k0 = (it + 1) * BK;
            a_pf  = *(const float4*)(xp  + k0);
            b1_pf = *(const float4*)(w1p + k0);
            b2_pf = *(const float4*)(w2p + k0);
        }

        #pragma unroll
        for (int kk = 0; kk < BK; kk++) {
            float4 a01 = *(const float4*)&As[p][kk][w * 8];
            float4 a23 = *(const float4*)&As[p][kk][w * 8 + 4];
            ulonglong2 bb = *(const ulonglong2*)&Bs[p][kk][lane * 4];
            float av[8] = {a01.x, a01.y, a01.z, a01.w,
                           a23.x, a23.y, a23.z, a23.w};
            #pragma unroll
            for (int i = 0; i < 8; i++) {
                ULL ad = pk2(av[i], av[i]);
                fma2(acc[i][0], ad, bb.x);
                fma2(acc[i][1], ad, bb.y);
            }
        }

        if (has_next) {
            const int q = p ^ 1;
            As[q][akc + 0][ar] = a_pf.x;  As[q][akc + 1][ar] = a_pf.y;
            As[q][akc + 2][ar] = a_pf.z;  As[q][akc + 3][ar] = a_pf.w;
            Bs[q][bkc + 0][bc] = b1_pf.x; Bs[q][bkc + 1][bc] = b1_pf.y;
            Bs[q][bkc + 2][bc] = b1_pf.z; Bs[q][bkc + 3][bc] = b1_pf.w;
            Bs[q][bkc + 0][bc + SK] = b2_pf.x; Bs[q][bkc + 1][bc + SK] = b2_pf.y;
            Bs[q][bkc + 2][bc + SK] = b2_pf.z; Bs[q][bkc + 3][bc + SK] = b2_pf.w;
            __syncthreads();
            p = q;
        }
    }

    #pragma unroll
    for (int i = 0; i < 8; i++) {
        const size_t row = (size_t)(bm0 + w * 8 + i);
        ulonglong2 v; v.x = acc[i][0]; v.y = acc[i][1];
        *(ulonglong2*)&g_S[row * (2 * SK) + lane * 4] = v;
    }
}

// ---------------------------------------------------------------------------
// Kernel B (R3 verbatim — measured 32us): one warp per row.
// 1) stream scores = s1[i]+s2[j] to GMEM (HBM-write bound, __stcs)
// 2) top-8 via decomposition: top8(s1) x top8(s2) -> 64 candidates -> top8.
//    Stable (lower-index) tie-breaks => matches jax.lax.top_k.
// ---------------------------------------------------------------------------
__global__ __launch_bounds__(256) void pkr_topk(
    float* __restrict__ idx_out,
    float* __restrict__ probs_out,
    float* __restrict__ scores_out)
{
    __shared__ float sb[8][2 * SK];
    __shared__ float c1v[8][8], c2v[8][8];
    __shared__ int   c1i[8][8], c2i[8][8];

    const int w    = threadIdx.x >> 5;
    const int lane = threadIdx.x & 31;
    const size_t row = (size_t)blockIdx.x * 8 + w;

    *(float4*)&sb[w][lane * 4] =
        *(const float4*)&g_S[row * (2 * SK) + lane * 4];
    __syncwarp();

    if (scores_out) {
        float* __restrict__ srow = scores_out + row * NEXPERT;
        const int j = (lane & 15) * 4;
        const float4 s2q = *(const float4*)&sb[w][SK + j];
        const int ihalf = lane >> 4;
        #pragma unroll 8
        for (int t = 0; t < 32; t++) {
            const int i = t * 2 + ihalf;
            const float s1 = sb[w][i];
            float4 v4;
            v4.x = s1 + s2q.x; v4.y = s1 + s2q.y;
            v4.z = s1 + s2q.z; v4.w = s1 + s2q.w;
            __stcs((float4*)&srow[i * SK + j], v4);
        }
    }

    {
        float a0 = sb[w][lane],      a1 = sb[w][lane + 32];
        int   i0 = lane,             i1 = lane + 32;
        float b0 = sb[w][SK + lane], b1 = sb[w][SK + lane + 32];
        int   j0 = lane,             j1 = lane + 32;
        #pragma unroll
        for (int r = 0; r < TOPK; r++) {
            float v; int i;
            if (a0 > a1 || (a0 == a1 && i0 < i1)) { v = a0; i = i0; }
            else                                  { v = a1; i = i1; }
            #pragma unroll
            for (int off = 16; off; off >>= 1) {
                float ov = __shfl_xor_sync(0xffffffffu, v, off);
                int   oi = __shfl_xor_sync(0xffffffffu, i, off);
                if (ov > v || (ov == v && oi < i)) { v = ov; i = oi; }
            }
            if (lane == r) { c1v[w][r] = v; c1i[w][r] = i; }
            if (i == i0) { a0 = -FLT_MAX; i0 = 1 << 30; }
            if (i == i1) { a1 = -FLT_MAX; i1 = 1 << 30; }
            float u; int jj;
            if (b0 > b1 || (b0 == b1 && j0 < j1)) { u = b0; jj = j0; }
            else                                  { u = b1; jj = j1; }
            #pragma unroll
            for (int off = 16; off; off >>= 1) {
                float ou = __shfl_xor_sync(0xffffffffu, u, off);
                int   oj = __shfl_xor_sync(0xffffffffu, jj, off);
                if (ou > u || (ou == u && oj < jj)) { u = ou; jj = oj; }
            }
            if (lane == r) { c2v[w][r] = u; c2i[w][r] = jj; }
            if (jj == j0) { b0 = -FLT_MAX; j0 = 1 << 30; }
            if (jj == j1) { b1 = -FLT_MAX; j1 = 1 << 30; }
        }
    }
    __syncwarp();

    const int p0 = lane, p1 = lane + 32;
    float cv0 = c1v[w][p0 >> 3] + c2v[w][p0 & 7];
    int   ci0 = c1i[w][p0 >> 3] * SK + c2i[w][p0 & 7];
    float cv1 = c1v[w][p1 >> 3] + c2v[w][p1 & 7];
    int   ci1 = c1i[w][p1 >> 3] * SK + c2i[w][p1 & 7];

    float mv[TOPK];
    int   mi[TOPK];
    #pragma unroll
    for (int r = 0; r < TOPK; r++) {
        float v; int i;
        if (cv0 > cv1 || (cv0 == cv1 && ci0 < ci1)) { v = cv0; i = ci0; }
        else                                        { v = cv1; i = ci1; }
        #pragma unroll
        for (int off = 16; off; off >>= 1) {
            float ov = __shfl_xor_sync(0xffffffffu, v, off);
            int   oi = __shfl_xor_sync(0xffffffffu, i, off);
            if (ov > v || (ov == v && oi < i)) { v = ov; i = oi; }
        }
        mv[r] = v; mi[r] = i;
        if (i == ci0) { cv0 = -FLT_MAX; ci0 = 1 << 30; }
        if (i == ci1) { cv1 = -FLT_MAX; ci1 = 1 << 30; }
    }

    if (lane == 0) {
        float m = mv[0], sum = 0.f, e[TOPK];
        #pragma unroll
        for (int r = 0; r < TOPK; r++) { e[r] = expf(mv[r] - m); sum += e[r]; }
        float inv = 1.f / sum;
        #pragma unroll
        for (int r = 0; r < TOPK; r++) {
            if (idx_out)   idx_out[row * TOPK + r]   = (float)mi[r];
            if (probs_out) probs_out[row * TOPK + r] = e[r] * inv;
        }
    }
}

// ---------------------------------------------------------------------------
extern "C" void kernel_launch(void* const* d_in, const int* in_sizes, int n_in,
                              void* d_out, int out_size) {
    const float* x  = (const float*)d_in[0];
    const float* W1 = (const float*)d_in[1];
    const float* W2 = (const float*)d_in[2];
    (void)n_in;

    int N = in_sizes[0] / D_DIM;   // 8192
    float* out = (float*)d_out;

    float* idxp = 0;
    float* probp = 0;
    float* scorep = 0;
    long long full = (long long)N * (2 * TOPK + NEXPERT);
    if ((long long)out_size == full) {
        idxp   = out;
        probp  = out + (long long)N * TOPK;
        scorep = out + (long long)N * 2 * TOPK;
    } else if ((long long)out_size == (long long)N * NEXPERT) {
        scorep = out;
    } else if ((long long)out_size == (long long)N * 2 * TOPK) {
        idxp  = out;
        probp = out + (long long)N * TOPK;
    } else {
        idxp   = out;
        probp  = out + (long long)N * TOPK;
        scorep = out + (long long)N * 2 * TOPK;
    }

    pkr_gemm<<<N / BM, 256>>>(x, W1, W2);
    pkr_topk<<<N / 8, 256>>>(idxp, probp, scorep);
}

// round 9
// speedup vs baseline: 1.5414x; 1.0461x over previous
#include <cuda_runtime.h>
#include <float.h>
#include <math.h>

// Problem constants (fixed shapes from reference setup_inputs)
#define D_DIM   2048
#define SK      64       // sqrt_K
#define NEXPERT 4096     // SK*SK
#define TOPK    8
#define NMAX    8192

typedef unsigned long long ULL;

// Scratch for fused projection S = x @ [W1;W2]^T  -> [N, 128]
__device__ float g_S[NMAX * 2 * SK];

// ---------------------------------------------------------------------------
// packed f32x2 helpers (exact fp32)
// ---------------------------------------------------------------------------
__device__ __forceinline__ ULL pk2(float lo, float hi) {
    ULL r;
    asm("mov.b64 %0, {%1, %2};" : "=l"(r) : "f"(lo), "f"(hi));
    return r;
}
__device__ __forceinline__ void fma2(ULL& d, ULL a, ULL b) {
    asm("fma.rn.f32x2 %0, %1, %2, %0;" : "+l"(d) : "l"(a), "l"(b));
}

// ---------------------------------------------------------------------------
// Kernel A (unchanged, measured 140us = fp32 FMA-pipe floor):
// SGEMM  S[N,128] = x[N,2048] @ concat(W1,W2)[128,2048]^T
// ---------------------------------------------------------------------------
#define BM 64
#define BN 128
#define BK 16
#define NIT (D_DIM / BK)

__global__ __launch_bounds__(256) void pkr_gemm(
    const float* __restrict__ x,
    const float* __restrict__ W1,
    const float* __restrict__ W2)
{
    __shared__ float As[2][BK][BM];
    __shared__ float Bs[2][BK][BN];

    const int tid  = threadIdx.x;
    const int w    = tid >> 5;
    const int lane = tid & 31;
    const int bm0  = blockIdx.x * BM;

    const int ar  = tid >> 2;
    const int akc = (tid & 3) * 4;
    const float* xp = x + (size_t)(bm0 + ar) * D_DIM + akc;

    const int bc  = tid & 63;
    const int bkc = (tid >> 6) * 4;
    const float* w1p = W1 + (size_t)bc * D_DIM + bkc;
    const float* w2p = W2 + (size_t)bc * D_DIM + bkc;

    ULL acc[8][2];
    #pragma unroll
    for (int i = 0; i < 8; i++) { acc[i][0] = 0ULL; acc[i][1] = 0ULL; }

    {
        float4 a  = *(const float4*)xp;
        float4 b1 = *(const float4*)w1p;
        float4 b2 = *(const float4*)w2p;
        As[0][akc + 0][ar] = a.x;  As[0][akc + 1][ar] = a.y;
        As[0][akc + 2][ar] = a.z;  As[0][akc + 3][ar] = a.w;
        Bs[0][bkc + 0][bc] = b1.x; Bs[0][bkc + 1][bc] = b1.y;
        Bs[0][bkc + 2][bc] = b1.z; Bs[0][bkc + 3][bc] = b1.w;
        Bs[0][bkc + 0][bc + SK] = b2.x; Bs[0][bkc + 1][bc + SK] = b2.y;
        Bs[0][bkc + 2][bc + SK] = b2.z; Bs[0][bkc + 3][bc + SK] = b2.w;
    }
    __syncthreads();

    int p = 0;
    float4 a_pf, b1_pf, b2_pf;
    for (int it = 0; it < NIT; ++it) {
        const bool has_next = (it + 1) < NIT;
        if (has_next) {
            const int k0 = (it + 1) * BK;
            a_pf  = *(const float4*)(xp  + k0);
            b1_pf = *(const float4*)(w1p + k0);
            b2_pf = *(const float4*)(w2p + k0);
        }

        #pragma unroll
        for (int kk = 0; kk < BK; kk++) {
            float4 a01 = *(const float4*)&As[p][kk][w * 8];
            float4 a23 = *(const float4*)&As[p][kk][w * 8 + 4];
            ulonglong2 bb = *(const ulonglong2*)&Bs[p][kk][lane * 4];
            float av[8] = {a01.x, a01.y, a01.z, a01.w,
                           a23.x, a23.y, a23.z, a23.w};
            #pragma unroll
            for (int i = 0; i < 8; i++) {
                ULL ad = pk2(av[i], av[i]);
                fma2(acc[i][0], ad, bb.x);
                fma2(acc[i][1], ad, bb.y);
            }
        }

        if (has_next) {
            const int q = p ^ 1;
            As[q][akc + 0][ar] = a_pf.x;  As[q][akc + 1][ar] = a_pf.y;
            As[q][akc + 2][ar] = a_pf.z;  As[q][akc + 3][ar] = a_pf.w;
            Bs[q][bkc + 0][bc] = b1_pf.x; Bs[q][bkc + 1][bc] = b1_pf.y;
            Bs[q][bkc + 2][bc] = b1_pf.z; Bs[q][bkc + 3][bc] = b1_pf.w;
            Bs[q][bkc + 0][bc + SK] = b2_pf.x; Bs[q][bkc + 1][bc + SK] = b2_pf.y;
            Bs[q][bkc + 2][bc + SK] = b2_pf.z; Bs[q][bkc + 3][bc + SK] = b2_pf.w;
            __syncthreads();
            p = q;
        }
    }

    #pragma unroll
    for (int i = 0; i < 8; i++) {
        const size_t row = (size_t)(bm0 + w * 8 + i);
        ulonglong2 v; v.x = acc[i][0]; v.y = acc[i][1];
        *(ulonglong2*)&g_S[row * (2 * SK) + lane * 4] = v;
    }
}

// ---------------------------------------------------------------------------
// Kernel B: one warp per row.  Score streaming is INTERLEAVED into the
// s1/s2 argmax rounds (4 stream iters per round) so LSU/L2 stalls and
// shfl-chain latency overlap.  Tie-breaks stable (lower index) everywhere.
// ---------------------------------------------------------------------------
__global__ __launch_bounds__(256) void pkr_topk(
    float* __restrict__ idx_out,
    float* __restrict__ probs_out,
    float* __restrict__ scores_out)
{
    __shared__ float sb[8][2 * SK];
    __shared__ float c1v[8][8], c2v[8][8];
    __shared__ int   c1i[8][8], c2i[8][8];

    const int w    = threadIdx.x >> 5;
    const int lane = threadIdx.x & 31;
    const size_t row = (size_t)blockIdx.x * 8 + w;

    *(float4*)&sb[w][lane * 4] =
        *(const float4*)&g_S[row * (2 * SK) + lane * 4];
    __syncwarp();

    // --- stream setup ---
    float* __restrict__ srow =
        scores_out ? scores_out + row * NEXPERT : (float*)0;
    const int j = (lane & 15) * 4;
    const float4 s2q = *(const float4*)&sb[w][SK + j];
    const int ihalf = lane >> 4;

    // --- topk state ---
    float a0 = sb[w][lane],      a1 = sb[w][lane + 32];
    int   i0 = lane,             i1 = lane + 32;
    float b0 = sb[w][SK + lane], b1 = sb[w][SK + lane + 32];
    int   j0 = lane,             j1 = lane + 32;

    #pragma unroll
    for (int r = 0; r < TOPK; r++) {
        // ---- 4 interleaved stream iterations (independent of rounds) ----
        if (srow) {
            #pragma unroll
            for (int u = 0; u < 4; u++) {
                const int t = r * 4 + u;
                const int i = t * 2 + ihalf;
                const float s1 = sb[w][i];
                float4 v4;
                v4.x = s1 + s2q.x; v4.y = s1 + s2q.y;
                v4.z = s1 + s2q.z; v4.w = s1 + s2q.w;
                __stcs((float4*)&srow[i * SK + j], v4);
            }
        }
        // ---- s1 round r ----
        {
            float v; int i;
            if (a0 > a1 || (a0 == a1 && i0 < i1)) { v = a0; i = i0; }
            else                                  { v = a1; i = i1; }
            #pragma unroll
            for (int off = 16; off; off >>= 1) {
                float ov = __shfl_xor_sync(0xffffffffu, v, off);
                int   oi = __shfl_xor_sync(0xffffffffu, i, off);
                if (ov > v || (ov == v && oi < i)) { v = ov; i = oi; }
            }
            if (lane == r) { c1v[w][r] = v; c1i[w][r] = i; }
            if (i == i0) { a0 = -FLT_MAX; i0 = 1 << 30; }
            if (i == i1) { a1 = -FLT_MAX; i1 = 1 << 30; }
        }
        // ---- s2 round r ----
        {
            float u; int jj;
            if (b0 > b1 || (b0 == b1 && j0 < j1)) { u = b0; jj = j0; }
            else                                  { u = b1; jj = j1; }
            #pragma unroll
            for (int off = 16; off; off >>= 1) {
                float ou = __shfl_xor_sync(0xffffffffu, u, off);
                int   oj = __shfl_xor_sync(0xffffffffu, jj, off);
                if (ou > u || (ou == u && oj < jj)) { u = ou; jj = oj; }
            }
            if (lane == r) { c2v[w][r] = u; c2i[w][r] = jj; }
            if (jj == j0) { b0 = -FLT_MAX; j0 = 1 << 30; }
            if (jj == j1) { b1 = -FLT_MAX; j1 = 1 << 30; }
        }
    }
    __syncwarp();

    // ---- top-8 of the 64 candidate pairs (2 per lane) ----
    const int p0 = lane, p1 = lane + 32;
    float cv0 = c1v[w][p0 >> 3] + c2v[w][p0 & 7];
    int   ci0 = c1i[w][p0 >> 3] * SK + c2i[w][p0 & 7];
    float cv1 = c1v[w][p1 >> 3] + c2v[w][p1 & 7];
    int   ci1 = c1i[w][p1 >> 3] * SK + c2i[w][p1 & 7];

    float mv[TOPK];
    int   mi[TOPK];
    #pragma unroll
    for (int r = 0; r < TOPK; r++) {
        float v; int i;
        if (cv0 > cv1 || (cv0 == cv1 && ci0 < ci1)) { v = cv0; i = ci0; }
        else                                        { v = cv1; i = ci1; }
        #pragma unroll
        for (int off = 16; off; off >>= 1) {
            float ov = __shfl_xor_sync(0xffffffffu, v, off);
            int   oi = __shfl_xor_sync(0xffffffffu, i, off);
            if (ov > v || (ov == v && oi < i)) { v = ov; i = oi; }
        }
        mv[r] = v; mi[r] = i;
        if (i == ci0) { cv0 = -FLT_MAX; ci0 = 1 << 30; }
        if (i == ci1) { cv1 = -FLT_MAX; ci1 = 1 << 30; }
    }

    if (lane == 0) {
        float m = mv[0], sum = 0.f, e[TOPK];
        #pragma unroll
        for (int r = 0; r < TOPK; r++) { e[r] = expf(mv[r] - m); sum += e[r]; }
        float inv = 1.f / sum;
        #pragma unroll
        for (int r = 0; r < TOPK; r++) {
            if (idx_out)   idx_out[row * TOPK + r]   = (float)mi[r];
            if (probs_out) probs_out[row * TOPK + r] = e[r] * inv;
        }
    }
}

// ---------------------------------------------------------------------------
extern "C" void kernel_launch(void* const* d_in, const int* in_sizes, int n_in,
                              void* d_out, int out_size) {
    const float* x  = (const float*)d_in[0];
    const float* W1 = (const float*)d_in[1];
    const float* W2 = (const float*)d_in[2];
    (void)n_in;

    int N = in_sizes[0] / D_DIM;   // 8192
    float* out = (float*)d_out;

    float* idxp = 0;
    float* probp = 0;
    float* scorep = 0;
    long long full = (long long)N * (2 * TOPK + NEXPERT);
    if ((long long)out_size == full) {
        idxp   = out;
        probp  = out + (long long)N * TOPK;
        scorep = out + (long long)N * 2 * TOPK;
    } else if ((long long)out_size == (long long)N * NEXPERT) {
        scorep = out;
    } else if ((long long)out_size == (long long)N * 2 * TOPK) {
        idxp  = out;
        probp = out + (long long)N * TOPK;
    } else {
        idxp   = out;
        probp  = out + (long long)N * TOPK;
        scorep = out + (long long)N * 2 * TOPK;
    }

    pkr_gemm<<<N / BM, 256>>>(x, W1, W2);
    pkr_topk<<<N / 8, 256>>>(idxp, probp, scorep);
}